// round 2
// baseline (speedup 1.0000x reference)
#include <cuda_runtime.h>
#include <math.h>

// Problem constants
#define PD 3
#define ND 4096
#define FD 1024
#define HD 8
#define DD 8
#define EMB 64      // H*D
#define ATTD 128
#define CD 16
#define MSEG 4      // m-dimension split for occupancy
#define TM 32       // m-chunk staged in smem

// ---------------- packed f32x2 helpers (Blackwell FFMA2/FMUL2/FADD2) ---------
__device__ __forceinline__ float2 f2mul(float2 a, float2 b) {
    float2 r;
    asm("mul.rn.f32x2 %0, %1, %2;"
        : "=l"(*reinterpret_cast<unsigned long long*>(&r))
        : "l"(*reinterpret_cast<unsigned long long*>(&a)),
          "l"(*reinterpret_cast<unsigned long long*>(&b)));
    return r;
}
__device__ __forceinline__ float2 f2add(float2 a, float2 b) {
    float2 r;
    asm("add.rn.f32x2 %0, %1, %2;"
        : "=l"(*reinterpret_cast<unsigned long long*>(&r))
        : "l"(*reinterpret_cast<unsigned long long*>(&a)),
          "l"(*reinterpret_cast<unsigned long long*>(&b)));
    return r;
}
__device__ __forceinline__ float2 f2fma(float2 a, float2 b, float2 c) {
    float2 r;
    asm("fma.rn.f32x2 %0, %1, %2, %3;"
        : "=l"(*reinterpret_cast<unsigned long long*>(&r))
        : "l"(*reinterpret_cast<unsigned long long*>(&a)),
          "l"(*reinterpret_cast<unsigned long long*>(&b)),
          "l"(*reinterpret_cast<unsigned long long*>(&c)));
    return r;
}
__device__ __forceinline__ float2 f2dup(float x) { return make_float2(x, x); }

// ---------------- scratch (static device memory; no allocations) -------------
__device__ __align__(16) float  g_fts [PD * ND * EMB];        // [p][n][h*8+d]
__device__ __align__(16) float2 g_ab1 [PD * ND * HD];         // (exp(f1), exp(0.01 f1))
__device__ __align__(16) float2 g_ab2 [PD * ND * HD];         // (exp(f2), exp(0.01 f2))
__device__ __align__(16) float  g_part[MSEG * PD * ND * 72];  // per-seg partial: 64 acc + 8 Z

// ---------------- K1: fts[p][n][c] = sum_f inputs[p][n][f] * W[p][c/8][f][c%8]
__global__ __launch_bounds__(256) void k1_gemm(const float* __restrict__ inp,
                                               const float* __restrict__ W) {
    const int p  = blockIdx.y;
    const int n0 = blockIdx.x * 64;
    __shared__ float As[32][68];   // [kk][row], padded
    __shared__ float Bs[32][64];   // [kk][col]
    const int tid = threadIdx.x;
    const int tx = tid & 15, ty = tid >> 4;
    float2 acc[4][2] = {};
    const float* Wp = W + (size_t)p * HD * FD * DD;

    for (int k0 = 0; k0 < FD; k0 += 32) {
        #pragma unroll
        for (int it = 0; it < 2; it++) {
            int idx = it * 256 + tid;
            int r = idx >> 3, q = idx & 7;
            float4 v = *reinterpret_cast<const float4*>(
                inp + ((size_t)(p * ND + n0 + r)) * FD + k0 + q * 4);
            As[q * 4 + 0][r] = v.x; As[q * 4 + 1][r] = v.y;
            As[q * 4 + 2][r] = v.z; As[q * 4 + 3][r] = v.w;
        }
        #pragma unroll
        for (int it = 0; it < 8; it++) {
            int idx = it * 256 + tid;
            int kk = idx >> 6, c = idx & 63;
            Bs[kk][c] = Wp[(size_t)(c >> 3) * (FD * DD) + (size_t)(k0 + kk) * DD + (c & 7)];
        }
        __syncthreads();
        #pragma unroll
        for (int kk = 0; kk < 32; kk++) {
            float4 a = *reinterpret_cast<const float4*>(&As[kk][ty * 4]);
            float4 b = *reinterpret_cast<const float4*>(&Bs[kk][tx * 4]);
            float2 b01 = make_float2(b.x, b.y), b23 = make_float2(b.z, b.w);
            float av[4] = {a.x, a.y, a.z, a.w};
            #pragma unroll
            for (int i = 0; i < 4; i++) {
                float2 ad = f2dup(av[i]);
                acc[i][0] = f2fma(ad, b01, acc[i][0]);
                acc[i][1] = f2fma(ad, b23, acc[i][1]);
            }
        }
        __syncthreads();
    }
    #pragma unroll
    for (int i = 0; i < 4; i++) {
        float4 v = make_float4(acc[i][0].x, acc[i][0].y, acc[i][1].x, acc[i][1].y);
        *reinterpret_cast<float4*>(
            g_fts + ((size_t)(p * ND + n0 + ty * 4 + i)) * EMB + tx * 4) = v;
    }
}

// ---------------- K1b: f1/f2 projections -> separable exp factors ------------
__global__ __launch_bounds__(256) void k1b_factors(const float* __restrict__ a1w,
                                                   const float* __restrict__ a1b,
                                                   const float* __restrict__ a2w,
                                                   const float* __restrict__ a2b) {
    const int p = blockIdx.y;
    const int tid = threadIdx.x;
    const int n = blockIdx.x * 32 + (tid >> 3);
    const int h = tid & 7;
    const float* f = g_fts + ((size_t)(p * ND + n)) * EMB + h * 8;
    float4 fa = *reinterpret_cast<const float4*>(f);
    float4 fb = *reinterpret_cast<const float4*>(f + 4);
    const float* w1 = a1w + (size_t)(p * HD + h) * DD;
    const float* w2 = a2w + (size_t)(p * HD + h) * DD;
    float f1 = a1b[p * HD + h];
    float f2 = a2b[p * HD + h];
    f1 += fa.x * w1[0] + fa.y * w1[1] + fa.z * w1[2] + fa.w * w1[3]
        + fb.x * w1[4] + fb.y * w1[5] + fb.z * w1[6] + fb.w * w1[7];
    f2 += fa.x * w2[0] + fa.y * w2[1] + fa.z * w2[2] + fa.w * w2[3]
        + fb.x * w2[4] + fb.y * w2[5] + fb.z * w2[6] + fb.w * w2[7];
    g_ab1[((size_t)p * ND + n) * HD + h] = make_float2(__expf(f1), __expf(0.01f * f1));
    g_ab2[((size_t)p * ND + n) * HD + h] = make_float2(__expf(f2), __expf(0.01f * f2));
}

// ---------------- K2: fused attention weights + aggregation ------------------
// CTA: 128 n-rows x 1024 m-range (mseg). 256 threads: h = tid&7, grp = tid>>3,
// each thread owns 4 consecutive n rows for one head. Packed f32x2 throughout.
__global__ __launch_bounds__(256, 2) void k2_attn(const float* __restrict__ bias) {
    const int p    = blockIdx.z;
    const int mseg = blockIdx.y;
    const int n0   = blockIdx.x * 128;
    const int tid  = threadIdx.x;
    const int h = tid & 7, grp = tid >> 3;

    __shared__ float  eb_s[TM][132];   // exp(bias) tile TRANSPOSED [mm][n_local], padded
    __shared__ float4 fts_s[TM][16];   // fts tile [mm][16 float4]
    __shared__ float2 f2_s[TM][8];     // (A2,B2) per [mm][h]

    float2 acc2[4][4] = {};            // [j][d-pair]
    float2 sum2[2] = {};               // (j0,j1),(j2,j3)
    float2 A1p[2], B1p[2];
    #pragma unroll
    for (int jp = 0; jp < 2; jp++) {
        float2 a0 = g_ab1[((size_t)p * ND + n0 + grp * 4 + 2 * jp)     * HD + h];
        float2 a1 = g_ab1[((size_t)p * ND + n0 + grp * 4 + 2 * jp + 1) * HD + h];
        A1p[jp] = make_float2(a0.x, a1.x);
        B1p[jp] = make_float2(a0.y, a1.y);
    }
    const float* brow = bias + ((size_t)p * ND + n0) * ND;

    const int m_begin = mseg * (ND / MSEG);
    const int m_end   = m_begin + (ND / MSEG);
    const int jm = tid & 31, wi = tid >> 5;

    for (int m0 = m_begin; m0 < m_end; m0 += TM) {
        // stage exp(bias) tile, transposed: eb_s[m_local][n_local]
        #pragma unroll
        for (int it = 0; it < 16; it++) {
            int i = it * 8 + wi;
            eb_s[jm][i] = __expf(brow[(size_t)i * ND + m0 + jm]);
        }
        // stage fts tile (32 m x 64)
        #pragma unroll
        for (int it = 0; it < 2; it++) {
            int idx = it * 256 + tid;
            int mm = idx >> 4, q = idx & 15;
            fts_s[mm][q] = *reinterpret_cast<const float4*>(
                g_fts + ((size_t)(p * ND + m0 + mm)) * EMB + q * 4);
        }
        {
            int mm = tid >> 3, hh = tid & 7;
            f2_s[mm][hh] = g_ab2[((size_t)p * ND + m0 + mm) * HD + hh];
        }
        __syncthreads();

        #pragma unroll 4
        for (int mm = 0; mm < TM; mm++) {
            float4 fa = fts_s[mm][2 * h];
            float4 fb = fts_s[mm][2 * h + 1];
            float2 ab2 = f2_s[mm][h];
            float4 eb4 = *reinterpret_cast<const float4*>(&eb_s[mm][grp * 4]);
            float2 faxy = make_float2(fa.x, fa.y), fazw = make_float2(fa.z, fa.w);
            float2 fbxy = make_float2(fb.x, fb.y), fbzw = make_float2(fb.z, fb.w);
            float2 a2x = f2dup(ab2.x), b2y = f2dup(ab2.y);
            #pragma unroll
            for (int jp = 0; jp < 2; jp++) {
                float2 t1 = f2mul(A1p[jp], a2x);
                float2 t2 = f2mul(B1p[jp], b2y);
                float2 mx = make_float2(fmaxf(t1.x, t2.x), fmaxf(t1.y, t2.y));
                float2 ebp = jp ? make_float2(eb4.z, eb4.w) : make_float2(eb4.x, eb4.y);
                float2 wp = f2mul(mx, ebp);
                sum2[jp] = f2add(sum2[jp], wp);
                float2 w0 = f2dup(wp.x), w1 = f2dup(wp.y);
                int j0 = 2 * jp, j1 = 2 * jp + 1;
                acc2[j0][0] = f2fma(w0, faxy, acc2[j0][0]);
                acc2[j0][1] = f2fma(w0, fazw, acc2[j0][1]);
                acc2[j0][2] = f2fma(w0, fbxy, acc2[j0][2]);
                acc2[j0][3] = f2fma(w0, fbzw, acc2[j0][3]);
                acc2[j1][0] = f2fma(w1, faxy, acc2[j1][0]);
                acc2[j1][1] = f2fma(w1, fazw, acc2[j1][1]);
                acc2[j1][2] = f2fma(w1, fbxy, acc2[j1][2]);
                acc2[j1][3] = f2fma(w1, fbzw, acc2[j1][3]);
            }
        }
        __syncthreads();
    }

    #pragma unroll
    for (int jp = 0; jp < 2; jp++) {
        #pragma unroll
        for (int q = 0; q < 2; q++) {
            int j = 2 * jp + q;
            float sj = q ? sum2[jp].y : sum2[jp].x;
            float* out = g_part + (((size_t)mseg * PD + p) * ND + n0 + grp * 4 + j) * 72;
            float4* o4 = reinterpret_cast<float4*>(out + h * 8);
            o4[0] = make_float4(acc2[j][0].x, acc2[j][0].y, acc2[j][1].x, acc2[j][1].y);
            o4[1] = make_float4(acc2[j][2].x, acc2[j][2].y, acc2[j][3].x, acc2[j][3].y);
            out[64 + h] = sj;
        }
    }
}

// ---------------- K3: normalize + ELU + semantic attention + classifier ------
// 4 rows per block; Ws cached in smem for reuse.
#define K3_ROWS 4
__global__ __launch_bounds__(128) void k3_final(const float* __restrict__ h_bias,
                                                const float* __restrict__ Ws,
                                                const float* __restrict__ bsv,
                                                const float* __restrict__ u,
                                                const float* __restrict__ Wc,
                                                const float* __restrict__ bc,
                                                float* __restrict__ out,
                                                int has_final, int has_alpha) {
    const int nbase = blockIdx.x * K3_ROWS;
    const int t = threadIdx.x;  // 128 threads
    __shared__ float Ws_s[EMB][ATTD];   // 32KB
    __shared__ float multi_s[PD][EMB];
    __shared__ float red[4 * PD];
    __shared__ float al[PD];
    __shared__ float fin[EMB];

    #pragma unroll
    for (int d = 0; d < EMB; d++) Ws_s[d][t] = Ws[d * ATTD + t];
    const float bs_t = bsv[t];
    const float u_t  = u[t];

    for (int r = 0; r < K3_ROWS; r++) {
        const int n = nbase + r;
        __syncthreads();
        // combine m-segment partials, normalize, add h_bias, ELU
        for (int idx = t; idx < PD * EMB; idx += 128) {
            int p = idx / EMB, d = idx % EMB, h = d >> 3;
            float a = 0.f, Z = 0.f;
            #pragma unroll
            for (int s = 0; s < MSEG; s++) {
                const float* b = g_part + (((size_t)s * PD + p) * ND + n) * 72;
                a += b[d];
                Z += b[64 + h];
            }
            float val = a / Z + h_bias[(p * HD + h) * DD + (d & 7)];
            multi_s[p][d] = val > 0.f ? val : expm1f(val);
        }
        __syncthreads();

        float partial[PD];
        #pragma unroll
        for (int p = 0; p < PD; p++) {
            float s = bs_t;
            #pragma unroll
            for (int d = 0; d < EMB; d++) s += multi_s[p][d] * Ws_s[d][t];
            partial[p] = tanhf(s) * u_t;
        }
        #pragma unroll
        for (int p = 0; p < PD; p++) {
            float v = partial[p];
            #pragma unroll
            for (int o = 16; o > 0; o >>= 1) v += __shfl_down_sync(0xffffffffu, v, o);
            if ((t & 31) == 0) red[(t >> 5) * PD + p] = v;
        }
        __syncthreads();
        if (t == 0) {
            float sc[PD];
            #pragma unroll
            for (int p = 0; p < PD; p++)
                sc[p] = red[p] + red[PD + p] + red[2 * PD + p] + red[3 * PD + p];
            float mx = fmaxf(sc[0], fmaxf(sc[1], sc[2]));
            float e0 = __expf(sc[0] - mx), e1 = __expf(sc[1] - mx), e2 = __expf(sc[2] - mx);
            float Zs = e0 + e1 + e2;
            al[0] = e0 / Zs; al[1] = e1 / Zs; al[2] = e2 / Zs;
        }
        __syncthreads();

        if (has_alpha && t < PD)
            out[(size_t)ND * (CD + EMB) + (size_t)n * PD + t] = al[t];

        if (t < EMB) {
            float f = al[0] * multi_s[0][t] + al[1] * multi_s[1][t] + al[2] * multi_s[2][t];
            fin[t] = f;
            if (has_final) out[(size_t)ND * CD + (size_t)n * EMB + t] = f;
        }
        __syncthreads();

        if (t < CD) {
            float s = bc[t];
            #pragma unroll
            for (int d = 0; d < EMB; d++) s += fin[d] * Wc[d * CD + t];
            out[(size_t)n * CD + t] = s;
        }
    }
}

// ---------------- launch ------------------------------------------------------
extern "C" void kernel_launch(void* const* d_in, const int* in_sizes, int n_in,
                              void* d_out, int out_size) {
    const float* inputs   = (const float*)d_in[0];   // [P,N,F]
    const float* bias_mat = (const float*)d_in[1];   // [P,N,N]
    const float* W        = (const float*)d_in[2];   // [P,H,F,D]
    const float* a1_w     = (const float*)d_in[3];   // [P,H,D]
    const float* a1_b     = (const float*)d_in[4];   // [P,H]
    const float* a2_w     = (const float*)d_in[5];
    const float* a2_b     = (const float*)d_in[6];
    const float* h_bias   = (const float*)d_in[7];   // [P,H,D]
    const float* Ws       = (const float*)d_in[8];   // [EMB,ATT]
    const float* bs       = (const float*)d_in[9];   // [ATT]
    const float* u        = (const float*)d_in[10];  // [ATT]
    const float* Wc       = (const float*)d_in[11];  // [EMB,C]
    const float* bc       = (const float*)d_in[12];  // [C]
    float* out = (float*)d_out;

    int has_final = (out_size >= ND * (CD + EMB)) ? 1 : 0;
    int has_alpha = (out_size >= ND * (CD + EMB + PD)) ? 1 : 0;

    k1_gemm   <<<dim3(ND / 64, PD), 256>>>(inputs, W);
    k1b_factors<<<dim3(ND / 32, PD), 256>>>(a1_w, a1_b, a2_w, a2_b);
    k2_attn   <<<dim3(ND / 128, MSEG, PD), 256>>>(bias_mat);
    k3_final  <<<ND / K3_ROWS, 128>>>(h_bias, Ws, bs, u, Wc, bc, out, has_final, has_alpha);
    (void)in_sizes; (void)n_in;
}

// round 5
// speedup vs baseline: 1.4751x; 1.4751x over previous
#include <cuda_runtime.h>
#include <math.h>
#include <stdint.h>

// Problem constants
#define PD 3
#define ND 4096
#define FD 1024
#define HD 8
#define DD 8
#define EMB 64
#define ATTD 128
#define CD 16
#define MSEG 8          // m-dimension split (768 CTAs)
#define KT 32           // m-chunk per ktile

// ---------------- scratch ----------------
__device__ __align__(16) float  g_fts [PD * ND * EMB];        // [p][n][h*8+d]
__device__ __align__(16) float2 g_ab1 [PD * ND * HD];         // (exp(f1), exp(0.01 f1))
__device__ __align__(16) float2 g_ab2 [PD * ND * HD];
__device__ __align__(16) float  g_part[MSEG * PD * ND * 72];  // 64 acc + 8 Z

// tf32 helpers (non-'a' PTX: works on compute_103)
__device__ __forceinline__ uint32_t to_tf32_rna(float f) {
    uint32_t r;
    asm("cvt.rna.tf32.f32 %0, %1;" : "=r"(r) : "f"(f));
    return r;
}
__device__ __forceinline__ float tf32_trunc(float f) {
    return __uint_as_float(__float_as_uint(f) & 0xFFFFE000u);
}
__device__ __forceinline__ void mma_tf32_16x8x8(float* d, uint32_t a0, uint32_t a1,
                                                uint32_t a2, uint32_t a3,
                                                uint32_t b0, uint32_t b1) {
    asm volatile(
        "mma.sync.aligned.m16n8k8.row.col.f32.tf32.tf32.f32 "
        "{%0,%1,%2,%3}, {%4,%5,%6,%7}, {%8,%9}, {%0,%1,%2,%3};"
        : "+f"(d[0]), "+f"(d[1]), "+f"(d[2]), "+f"(d[3])
        : "r"(a0), "r"(a1), "r"(a2), "r"(a3), "r"(b0), "r"(b1));
}

// ---------------- K1: projection GEMM -----------------------------------------
__global__ __launch_bounds__(256) void k1_gemm(const float* __restrict__ inp,
                                               const float* __restrict__ W) {
    const int p  = blockIdx.y;
    const int n0 = blockIdx.x * 64;
    __shared__ float As[32][68];
    __shared__ float Bs[32][64];
    const int tid = threadIdx.x;
    const int tx = tid & 15, ty = tid >> 4;
    float acc[4][4] = {};
    const float* Wp = W + (size_t)p * HD * FD * DD;

    for (int k0 = 0; k0 < FD; k0 += 32) {
        #pragma unroll
        for (int it = 0; it < 2; it++) {
            int idx = it * 256 + tid;
            int r = idx >> 3, q = idx & 7;
            float4 v = *reinterpret_cast<const float4*>(
                inp + ((size_t)(p * ND + n0 + r)) * FD + k0 + q * 4);
            As[q * 4 + 0][r] = v.x; As[q * 4 + 1][r] = v.y;
            As[q * 4 + 2][r] = v.z; As[q * 4 + 3][r] = v.w;
        }
        #pragma unroll
        for (int it = 0; it < 8; it++) {
            int idx = it * 256 + tid;
            int kk = idx >> 6, c = idx & 63;
            Bs[kk][c] = Wp[(size_t)(c >> 3) * (FD * DD) + (size_t)(k0 + kk) * DD + (c & 7)];
        }
        __syncthreads();
        #pragma unroll
        for (int kk = 0; kk < 32; kk++) {
            float4 a = *reinterpret_cast<const float4*>(&As[kk][ty * 4]);
            float4 b = *reinterpret_cast<const float4*>(&Bs[kk][tx * 4]);
            float av[4] = {a.x, a.y, a.z, a.w};
            float bv[4] = {b.x, b.y, b.z, b.w};
            #pragma unroll
            for (int i = 0; i < 4; i++)
                #pragma unroll
                for (int j = 0; j < 4; j++)
                    acc[i][j] += av[i] * bv[j];
        }
        __syncthreads();
    }
    #pragma unroll
    for (int i = 0; i < 4; i++) {
        float4 v = make_float4(acc[i][0], acc[i][1], acc[i][2], acc[i][3]);
        *reinterpret_cast<float4*>(
            g_fts + ((size_t)(p * ND + n0 + ty * 4 + i)) * EMB + tx * 4) = v;
    }
}

// ---------------- K1b: f1/f2 projections -> separable exp factors -------------
__global__ __launch_bounds__(256) void k1b_factors(const float* __restrict__ a1w,
                                                   const float* __restrict__ a1b,
                                                   const float* __restrict__ a2w,
                                                   const float* __restrict__ a2b) {
    const int p = blockIdx.y;
    const int tid = threadIdx.x;
    const int n = blockIdx.x * 32 + (tid >> 3);
    const int h = tid & 7;
    const float* f = g_fts + ((size_t)(p * ND + n)) * EMB + h * 8;
    float4 fa = *reinterpret_cast<const float4*>(f);
    float4 fb = *reinterpret_cast<const float4*>(f + 4);
    const float* w1 = a1w + (size_t)(p * HD + h) * DD;
    const float* w2 = a2w + (size_t)(p * HD + h) * DD;
    float f1 = a1b[p * HD + h];
    float f2 = a2b[p * HD + h];
    f1 += fa.x * w1[0] + fa.y * w1[1] + fa.z * w1[2] + fa.w * w1[3]
        + fb.x * w1[4] + fb.y * w1[5] + fb.z * w1[6] + fb.w * w1[7];
    f2 += fa.x * w2[0] + fa.y * w2[1] + fa.z * w2[2] + fa.w * w2[3]
        + fb.x * w2[4] + fb.y * w2[5] + fb.z * w2[6] + fb.w * w2[7];
    g_ab1[((size_t)p * ND + n) * HD + h] = make_float2(__expf(f1), __expf(0.01f * f1));
    g_ab2[((size_t)p * ND + n) * HD + h] = make_float2(__expf(f2), __expf(0.01f * f2));
}

// ---------------- K2: mma.sync tf32 attention ---------------------------------
// CTA = (p, mseg, 128n). warp w = head h. Per ktile (32 m):
//   D[16n,8d] per ntile (8 ntiles) accumulated via m16n8k8 tf32 mma,
//   A fragment = attention weights generated in registers,
//   row-sums via FADD on the tf32-truncated weights.
__global__ __launch_bounds__(256, 2) void k2_attn_mma(const float* __restrict__ bias) {
    const int p    = blockIdx.z;
    const int mseg = blockIdx.y;
    const int n0   = blockIdx.x * 128;
    const int tid  = threadIdx.x;
    const int h    = tid >> 5;          // warp = head
    const int lane = tid & 31;
    const int g = lane >> 2, c = lane & 3;

    __shared__ float  eb_s [32 * 136];   // exp(bias) [m][n], stride 136 (bank-clean)
    __shared__ float  fts_s[32 * 72];    // fts tf32 [m][d64], stride 72 (bank-clean)
    __shared__ float2 ab1_s[128 * 9];    // (A1,B1)   [n][h], stride 9 (bank-clean)
    __shared__ float2 f2_s [32 * 9];     // (A2,B2)   [m][h], stride 9 (bank-clean)

    float D[8][4];                        // [ntile][c0,c1,c2,c3]
    float sum0[8], sum1[8];
    #pragma unroll
    for (int nt = 0; nt < 8; nt++) {
        D[nt][0] = D[nt][1] = D[nt][2] = D[nt][3] = 0.f;
        sum0[nt] = sum1[nt] = 0.f;
    }

    // stage ab1 once
    for (int i = tid; i < 128 * 8; i += 256) {
        int n = i >> 3, hh = i & 7;
        ab1_s[n * 9 + hh] = g_ab1[((size_t)p * ND + n0 + n) * HD + hh];
    }

    const float* brow = bias + ((size_t)p * ND + n0) * ND;
    const int n_loc = tid >> 1, kh = tid & 1;
    const int m_base = mseg * (ND / MSEG);

    for (int kt = 0; kt < (ND / MSEG) / KT; kt++) {
        const int m0 = m_base + kt * KT;
        __syncthreads();
        // stage exp(bias): thread covers (n_loc, 16 m), write transposed [m][n]
        {
            const float* bp = brow + (size_t)n_loc * ND + m0 + kh * 16;
            #pragma unroll
            for (int q = 0; q < 4; q++) {
                float4 v = *reinterpret_cast<const float4*>(bp + q * 4);
                int mm = kh * 16 + q * 4;
                eb_s[(mm + 0) * 136 + n_loc] = __expf(v.x);
                eb_s[(mm + 1) * 136 + n_loc] = __expf(v.y);
                eb_s[(mm + 2) * 136 + n_loc] = __expf(v.z);
                eb_s[(mm + 3) * 136 + n_loc] = __expf(v.w);
            }
        }
        // stage fts tile (32 m x 64 d = 512 float4 quads), rounded to tf32
        #pragma unroll
        for (int it = 0; it < 2; it++) {
            int idx = it * 256 + tid;
            int mm = idx >> 4, q = idx & 15;
            float4 v = *reinterpret_cast<const float4*>(
                g_fts + ((size_t)(p * ND + m0 + mm)) * EMB + q * 4);
            uint32_t* dst = (uint32_t*)&fts_s[mm * 72 + q * 4];
            dst[0] = to_tf32_rna(v.x); dst[1] = to_tf32_rna(v.y);
            dst[2] = to_tf32_rna(v.z); dst[3] = to_tf32_rna(v.w);
        }
        // stage (A2,B2) [32][h]
        {
            int mm = tid >> 3, hh = tid & 7;
            f2_s[mm * 9 + hh] = g_ab2[((size_t)p * ND + m0 + mm) * HD + hh];
        }
        __syncthreads();

        #pragma unroll
        for (int s = 0; s < 4; s++) {
            const int mlo = s * 8 + c;
            // B fragment for this head
            uint32_t b0 = __float_as_uint(fts_s[mlo * 72 + h * 8 + g]);
            uint32_t b1 = __float_as_uint(fts_s[(mlo + 4) * 72 + h * 8 + g]);
            float2 ylo = f2_s[mlo * 9 + h];
            float2 yhi = f2_s[(mlo + 4) * 9 + h];
            const float* ebp = eb_s + mlo * 136 + g;

            #pragma unroll
            for (int nt = 0; nt < 8; nt++) {
                float2 x0 = ab1_s[(nt * 16 + g) * 9 + h];
                float2 x1 = ab1_s[(nt * 16 + 8 + g) * 9 + h];
                float e00 = ebp[nt * 16];
                float e01 = ebp[4 * 136 + nt * 16];
                float e10 = ebp[nt * 16 + 8];
                float e11 = ebp[4 * 136 + nt * 16 + 8];
                float w0 = tf32_trunc(fmaxf(x0.x * ylo.x, x0.y * ylo.y) * e00);
                float w2 = tf32_trunc(fmaxf(x0.x * yhi.x, x0.y * yhi.y) * e01);
                float w1 = tf32_trunc(fmaxf(x1.x * ylo.x, x1.y * ylo.y) * e10);
                float w3 = tf32_trunc(fmaxf(x1.x * yhi.x, x1.y * yhi.y) * e11);
                sum0[nt] += w0 + w2;
                sum1[nt] += w1 + w3;
                mma_tf32_16x8x8(D[nt], __float_as_uint(w0), __float_as_uint(w1),
                                __float_as_uint(w2), __float_as_uint(w3), b0, b1);
            }
        }
    }

    // epilogue: D fragments + reduced sums -> g_part
    #pragma unroll
    for (int nt = 0; nt < 8; nt++) {
        float s0 = sum0[nt], s1 = sum1[nt];
        s0 += __shfl_xor_sync(0xffffffffu, s0, 1);
        s0 += __shfl_xor_sync(0xffffffffu, s0, 2);
        s1 += __shfl_xor_sync(0xffffffffu, s1, 1);
        s1 += __shfl_xor_sync(0xffffffffu, s1, 2);
        int r0 = n0 + nt * 16 + g, r1 = r0 + 8;
        float* op0 = g_part + (((size_t)mseg * PD + p) * ND + r0) * 72;
        float* op1 = g_part + (((size_t)mseg * PD + p) * ND + r1) * 72;
        *reinterpret_cast<float2*>(op0 + h * 8 + 2 * c) = make_float2(D[nt][0], D[nt][1]);
        *reinterpret_cast<float2*>(op1 + h * 8 + 2 * c) = make_float2(D[nt][2], D[nt][3]);
        if (c == 0) { op0[64 + h] = s0; op1[64 + h] = s1; }
    }
}

// ---------------- K3: combine + ELU + semantic attention + classifier ---------
__global__ __launch_bounds__(128) void k3_final(const float* __restrict__ h_bias,
                                                const float* __restrict__ Ws,
                                                const float* __restrict__ bsv,
                                                const float* __restrict__ u,
                                                const float* __restrict__ Wc,
                                                const float* __restrict__ bc,
                                                float* __restrict__ out,
                                                int has_final, int has_alpha) {
    const int n = blockIdx.x;
    const int t = threadIdx.x;
    __shared__ float multi_s[PD][EMB];
    __shared__ float red[4 * PD];
    __shared__ float al[PD];
    __shared__ float fin[EMB];

    for (int idx = t; idx < PD * EMB; idx += 128) {
        int p = idx / EMB, d = idx % EMB, h = d >> 3;
        float a = 0.f, Z = 0.f;
        #pragma unroll
        for (int s = 0; s < MSEG; s++) {
            const float* b = g_part + (((size_t)s * PD + p) * ND + n) * 72;
            a += b[d];
            Z += b[64 + h];
        }
        float val = a / Z + h_bias[(p * HD + h) * DD + (d & 7)];
        multi_s[p][d] = val > 0.f ? val : expm1f(val);
    }
    __syncthreads();

    float partial[PD];
    #pragma unroll
    for (int p = 0; p < PD; p++) {
        float s = bsv[t];
        #pragma unroll
        for (int d = 0; d < EMB; d++) s += multi_s[p][d] * Ws[d * ATTD + t];
        partial[p] = tanhf(s) * u[t];
    }
    #pragma unroll
    for (int p = 0; p < PD; p++) {
        float v = partial[p];
        #pragma unroll
        for (int o = 16; o > 0; o >>= 1) v += __shfl_down_sync(0xffffffffu, v, o);
        if ((t & 31) == 0) red[(t >> 5) * PD + p] = v;
    }
    __syncthreads();
    if (t == 0) {
        float sc[PD];
        #pragma unroll
        for (int p = 0; p < PD; p++)
            sc[p] = red[p] + red[PD + p] + red[2 * PD + p] + red[3 * PD + p];
        float mx = fmaxf(sc[0], fmaxf(sc[1], sc[2]));
        float e0 = __expf(sc[0] - mx), e1 = __expf(sc[1] - mx), e2 = __expf(sc[2] - mx);
        float Zs = e0 + e1 + e2;
        al[0] = e0 / Zs; al[1] = e1 / Zs; al[2] = e2 / Zs;
    }
    __syncthreads();

    if (has_alpha && t < PD)
        out[(size_t)ND * (CD + EMB) + (size_t)n * PD + t] = al[t];

    if (t < EMB) {
        float f = al[0] * multi_s[0][t] + al[1] * multi_s[1][t] + al[2] * multi_s[2][t];
        fin[t] = f;
        if (has_final) out[(size_t)ND * CD + (size_t)n * EMB + t] = f;
    }
    __syncthreads();

    if (t < CD) {
        float s = bc[t];
        #pragma unroll
        for (int d = 0; d < EMB; d++) s += fin[d] * Wc[d * CD + t];
        out[(size_t)n * CD + t] = s;
    }
}

// ---------------- launch ------------------------------------------------------
extern "C" void kernel_launch(void* const* d_in, const int* in_sizes, int n_in,
                              void* d_out, int out_size) {
    const float* inputs   = (const float*)d_in[0];
    const float* bias_mat = (const float*)d_in[1];
    const float* W        = (const float*)d_in[2];
    const float* a1_w     = (const float*)d_in[3];
    const float* a1_b     = (const float*)d_in[4];
    const float* a2_w     = (const float*)d_in[5];
    const float* a2_b     = (const float*)d_in[6];
    const float* h_bias   = (const float*)d_in[7];
    const float* Ws       = (const float*)d_in[8];
    const float* bs       = (const float*)d_in[9];
    const float* u        = (const float*)d_in[10];
    const float* Wc       = (const float*)d_in[11];
    const float* bc       = (const float*)d_in[12];
    float* out = (float*)d_out;

    int has_final = (out_size >= ND * (CD + EMB)) ? 1 : 0;
    int has_alpha = (out_size >= ND * (CD + EMB + PD)) ? 1 : 0;

    k1_gemm    <<<dim3(ND / 64, PD), 256>>>(inputs, W);
    k1b_factors<<<dim3(ND / 32, PD), 256>>>(a1_w, a1_b, a2_w, a2_b);
    k2_attn_mma<<<dim3(ND / 128, MSEG, PD), 256>>>(bias_mat);
    k3_final   <<<ND, 128>>>(h_bias, Ws, bs, u, Wc, bc, out, has_final, has_alpha);
    (void)in_sizes; (void)n_in;
}